// round 5
// baseline (speedup 1.0000x reference)
#include <cuda_runtime.h>
#include <cuda_fp16.h>

#define D 64
#define NMAX 50000
#define EMAX 1250000
#define TILE_M 128
#define S_T 132
#define SCAN_BLOCK 1024

// ---------------- device scratch (no allocation allowed) ----------------
__device__ __half g_mh[NMAX * D];     // per-node message table (fp16)
__device__ float  g_z[NMAX * D];      // segment-sum result (fp32)
__device__ int    g_hist[NMAX + 1];
__device__ int    g_off[NMAX + 1];    // CSR offsets
__device__ int    g_cursor[NMAX];
__device__ int    g_src_sorted[EMAX];
__device__ unsigned long long g_scan_state[64];  // (flag<<32)|value

// Dynamic SMEM (floats): XH[64][S_T], W1s, W2s, b1s, b2s
#define SMEM_FLOATS (64 * S_T + 2 * 64 * 64 + 128)
#define SMEM_BYTES  (SMEM_FLOATS * 4)

// ---------------------------------------------------------------------------
// Fused 2-layer MLP, register-blocked tiled GEMM (same as R4).
// ---------------------------------------------------------------------------
template <typename OutT>
__global__ __launch_bounds__(256, 3) void mlp2_tiled_kernel(
    const float* __restrict__ in,
    const float* __restrict__ W1, const float* __restrict__ b1,
    const float* __restrict__ W2, const float* __restrict__ b2,
    OutT* __restrict__ out, int n)
{
    extern __shared__ float smem[];
    float* XH  = smem;
    float* W1s = XH + 64 * S_T;
    float* W2s = W1s + 4096;
    float* b1s = W2s + 4096;
    float* b2s = b1s + 64;

    const int tid = threadIdx.x;
    const int m0  = blockIdx.x * TILE_M;

#pragma unroll
    for (int p = tid; p < 1024; p += 256) {
        ((float4*)W1s)[p] = ((const float4*)W1)[p];
        ((float4*)W2s)[p] = ((const float4*)W2)[p];
    }
    if (tid < 64) {
        b1s[tid] = b1[tid];
        b2s[tid] = b2[tid];
    }

#pragma unroll
    for (int p = tid; p < TILE_M * 16; p += 256) {
        const int m  = p >> 4;
        const int kq = p & 15;
        float4 v = make_float4(0.f, 0.f, 0.f, 0.f);
        if (m0 + m < n) v = ((const float4*)in)[(size_t)(m0 + m) * 16 + kq];
        const int k = kq * 4;
        XH[(k + 0) * S_T + m] = v.x;
        XH[(k + 1) * S_T + m] = v.y;
        XH[(k + 2) * S_T + m] = v.z;
        XH[(k + 3) * S_T + m] = v.w;
    }
    __syncthreads();

    const int tn = tid & 15;
    const int tm = tid >> 4;
    const int cbase = tn * 4;
    const int mbase = tm * 8;

    float acc[4][8];

#pragma unroll
    for (int j = 0; j < 4; j++)
#pragma unroll
        for (int i = 0; i < 8; i++) acc[j][i] = 0.f;

#pragma unroll 8
    for (int k = 0; k < 64; k++) {
        const float4 a0 = *(const float4*)&XH[k * S_T + mbase];
        const float4 a1 = *(const float4*)&XH[k * S_T + mbase + 4];
        const float4 b  = *(const float4*)&W1s[k * 64 + cbase];
        const float a[8] = {a0.x, a0.y, a0.z, a0.w, a1.x, a1.y, a1.z, a1.w};
        const float bb[4] = {b.x, b.y, b.z, b.w};
#pragma unroll
        for (int j = 0; j < 4; j++)
#pragma unroll
            for (int i = 0; i < 8; i++)
                acc[j][i] = fmaf(a[i], bb[j], acc[j][i]);
    }

    __syncthreads();

#pragma unroll
    for (int j = 0; j < 4; j++) {
        const float bj = b1s[cbase + j];
#pragma unroll
        for (int i = 0; i < 8; i++) acc[j][i] = fmaxf(acc[j][i] + bj, 0.f);
        *(float4*)&XH[(cbase + j) * S_T + mbase] =
            make_float4(acc[j][0], acc[j][1], acc[j][2], acc[j][3]);
        *(float4*)&XH[(cbase + j) * S_T + mbase + 4] =
            make_float4(acc[j][4], acc[j][5], acc[j][6], acc[j][7]);
    }
    __syncthreads();

#pragma unroll
    for (int j = 0; j < 4; j++)
#pragma unroll
        for (int i = 0; i < 8; i++) acc[j][i] = 0.f;

#pragma unroll 8
    for (int k = 0; k < 64; k++) {
        const float4 a0 = *(const float4*)&XH[k * S_T + mbase];
        const float4 a1 = *(const float4*)&XH[k * S_T + mbase + 4];
        const float4 b  = *(const float4*)&W2s[k * 64 + cbase];
        const float a[8] = {a0.x, a0.y, a0.z, a0.w, a1.x, a1.y, a1.z, a1.w};
        const float bb[4] = {b.x, b.y, b.z, b.w};
#pragma unroll
        for (int j = 0; j < 4; j++)
#pragma unroll
            for (int i = 0; i < 8; i++)
                acc[j][i] = fmaf(a[i], bb[j], acc[j][i]);
    }

#pragma unroll
    for (int j = 0; j < 4; j++) {
        const float bj = b2s[cbase + j];
#pragma unroll
        for (int i = 0; i < 8; i++) acc[j][i] = fmaxf(acc[j][i] + bj, 0.f);
    }

#pragma unroll
    for (int i = 0; i < 8; i++) {
        const int m = m0 + mbase + i;
        if (m < n) {
            if constexpr (sizeof(OutT) == 4) {
                *(float4*)&out[(size_t)m * 64 + cbase] =
                    make_float4(acc[0][i], acc[1][i], acc[2][i], acc[3][i]);
            } else {
                __half2 h01 = __floats2half2_rn(acc[0][i], acc[1][i]);
                __half2 h23 = __floats2half2_rn(acc[2][i], acc[3][i]);
                uint2 u;
                u.x = *(unsigned int*)&h01;
                u.y = *(unsigned int*)&h23;
                *(uint2*)&out[(size_t)m * 64 + cbase] = u;
            }
        }
    }
}

// ---------------------------------------------------------------------------
// Histogram of dst (vectorized int4 loads) + zero the scan state flags.
// ---------------------------------------------------------------------------
__global__ __launch_bounds__(256) void hist_kernel(const int4* __restrict__ dst4,
                                                   int e4, int e,
                                                   const int* __restrict__ dst) {
    const int i = blockIdx.x * blockDim.x + threadIdx.x;
    if (blockIdx.x == 0 && threadIdx.x < 64) g_scan_state[threadIdx.x] = 0ULL;
    if (i < e4) {
        const int4 d = dst4[i];
        asm volatile("red.global.add.s32 [%0], 1;" :: "l"(&g_hist[d.x]) : "memory");
        asm volatile("red.global.add.s32 [%0], 1;" :: "l"(&g_hist[d.y]) : "memory");
        asm volatile("red.global.add.s32 [%0], 1;" :: "l"(&g_hist[d.z]) : "memory");
        asm volatile("red.global.add.s32 [%0], 1;" :: "l"(&g_hist[d.w]) : "memory");
    }
    // remainder
    const int r = e4 * 4 + i;
    if (i < e - e4 * 4) {
        asm volatile("red.global.add.s32 [%0], 1;" :: "l"(&g_hist[dst[r]]) : "memory");
    }
}

__device__ __forceinline__ int warp_incl_scan(int v, int lane) {
#pragma unroll
    for (int d = 1; d < 32; d <<= 1) {
        int t = __shfl_up_sync(0xffffffffu, v, d);
        if (lane >= d) v += t;
    }
    return v;
}

// ---------------------------------------------------------------------------
// Single-pass exclusive scan with decoupled lookback.
// 1024 threads/block; <=49 blocks; flags packed (flag<<32)|sum.
// flag: 0=invalid, 1=aggregate ready, 2=inclusive prefix ready.
// ---------------------------------------------------------------------------
__global__ __launch_bounds__(SCAN_BLOCK) void scan_lookback_kernel(int n) {
    __shared__ int wsum[32];
    __shared__ int s_prefix;

    const int b = blockIdx.x;
    const int tid = threadIdx.x;
    const int lane = tid & 31;
    const int wid = tid >> 5;
    const int g = b * SCAN_BLOCK + tid;

    const int x = (g < n) ? g_hist[g] : 0;
    int incl = warp_incl_scan(x, lane);
    if (lane == 31) wsum[wid] = incl;
    __syncthreads();
    if (wid == 0) wsum[lane] = warp_incl_scan(wsum[lane], lane);
    __syncthreads();

    const int block_excl = incl - x + ((wid > 0) ? wsum[wid - 1] : 0);
    const int block_total = wsum[31];

    if (tid == 0) {
        if (b == 0) {
            atomicExch(&g_scan_state[0],
                       (2ULL << 32) | (unsigned long long)(unsigned)block_total);
            s_prefix = 0;
        } else {
            atomicExch(&g_scan_state[b],
                       (1ULL << 32) | (unsigned long long)(unsigned)block_total);
            int prefix = 0;
            int j = b - 1;
            while (true) {
                unsigned long long v = atomicAdd(&g_scan_state[j], 0ULL);
                const unsigned flag = (unsigned)(v >> 32);
                if (flag == 0) continue;
                prefix += (int)(unsigned)v;
                if (flag == 2) break;
                j--;
            }
            atomicExch(&g_scan_state[b],
                       (2ULL << 32) |
                       (unsigned long long)(unsigned)(prefix + block_total));
            s_prefix = prefix;
        }
    }
    __syncthreads();

    const int excl = s_prefix + block_excl;
    if (g < n) {
        g_off[g] = excl;
        g_cursor[g] = excl;
    }
    if (g == n - 1) g_off[n] = excl + x;
}

// ---------------------------------------------------------------------------
// Reorder src by dst bucket (vectorized loads).
// ---------------------------------------------------------------------------
__global__ __launch_bounds__(256) void reorder_kernel(
    const int4* __restrict__ src4, const int4* __restrict__ dst4,
    int e4, int e, const int* __restrict__ src, const int* __restrict__ dst)
{
    const int i = blockIdx.x * blockDim.x + threadIdx.x;
    if (i < e4) {
        const int4 s = src4[i];
        const int4 d = dst4[i];
        g_src_sorted[atomicAdd(&g_cursor[d.x], 1)] = s.x;
        g_src_sorted[atomicAdd(&g_cursor[d.y], 1)] = s.y;
        g_src_sorted[atomicAdd(&g_cursor[d.z], 1)] = s.z;
        g_src_sorted[atomicAdd(&g_cursor[d.w], 1)] = s.w;
    }
    const int r = e4 * 4 + i;
    if (i < e - e4 * 4) {
        g_src_sorted[atomicAdd(&g_cursor[dst[r]], 1)] = src[r];
    }
}

// ---------------------------------------------------------------------------
// CSR aggregation: warp per node, fp16 gather, fp32 accumulation.
// ---------------------------------------------------------------------------
__global__ __launch_bounds__(256) void aggregate_kernel(
    const __half2* __restrict__ m2, float2* __restrict__ z2, int n)
{
    const int warp = (blockIdx.x * 256 + threadIdx.x) >> 5;
    const int lane = threadIdx.x & 31;
    if (warp >= n) return;

    const int s0 = g_off[warp];
    const int s1 = g_off[warp + 1];

    float ax = 0.f, ay = 0.f;
    for (int base = s0; base < s1; base += 32) {
        const int cnt = min(32, s1 - base);
        int si = (lane < cnt) ? g_src_sorted[base + lane] : 0;
#pragma unroll 4
        for (int j = 0; j < cnt; j++) {
            const int s = __shfl_sync(0xffffffffu, si, j);
            const __half2 h = __ldg(&m2[(size_t)s * 32 + lane]);
            const float2 v = __half22float2(h);
            ax += v.x;
            ay += v.y;
        }
    }
    float2 o;
    o.x = ax;
    o.y = ay;
    z2[(size_t)warp * 32 + lane] = o;
}

// ---------------------------------------------------------------------------
extern "C" void kernel_launch(void* const* d_in, const int* in_sizes, int n_in,
                              void* d_out, int out_size) {
    const float* y   = (const float*)d_in[0];
    const int*   src = (const int*)d_in[1];
    const int*   dst = (const int*)d_in[2];
    const float* W1  = (const float*)d_in[3];
    const float* b1  = (const float*)d_in[4];
    const float* W2  = (const float*)d_in[5];
    const float* b2  = (const float*)d_in[6];
    const float* U1  = (const float*)d_in[7];
    const float* c1  = (const float*)d_in[8];
    const float* U2  = (const float*)d_in[9];
    const float* c2  = (const float*)d_in[10];
    float* out = (float*)d_out;

    const int n = in_sizes[0] / D;
    const int e = in_sizes[1];
    const int e4 = e / 4;

    __half* mh_ptr = nullptr;
    float*  z_ptr  = nullptr;
    int*    hist_ptr = nullptr;
    cudaGetSymbolAddress((void**)&mh_ptr, g_mh);
    cudaGetSymbolAddress((void**)&z_ptr, g_z);
    cudaGetSymbolAddress((void**)&hist_ptr, g_hist);

    cudaFuncSetAttribute(mlp2_tiled_kernel<__half>,
                         cudaFuncAttributeMaxDynamicSharedMemorySize, SMEM_BYTES);
    cudaFuncSetAttribute(mlp2_tiled_kernel<float>,
                         cudaFuncAttributeMaxDynamicSharedMemorySize, SMEM_BYTES);

    static cudaStream_t s_side = ([] {
        cudaStream_t s;
        cudaStreamCreateWithFlags(&s, cudaStreamNonBlocking);
        return s;
    })();
    static cudaEvent_t ev_fork = ([] {
        cudaEvent_t ev;
        cudaEventCreateWithFlags(&ev, cudaEventDisableTiming);
        return ev;
    })();
    static cudaEvent_t ev_join = ([] {
        cudaEvent_t ev;
        cudaEventCreateWithFlags(&ev, cudaEventDisableTiming);
        return ev;
    })();

    const int mlp_blocks = (n + TILE_M - 1) / TILE_M;
    const int nb = (n + SCAN_BLOCK - 1) / SCAN_BLOCK;
    const int ev_threads = e4 + 256;  // covers vector part and remainder

    // ---- fork: sort pipeline on side stream ----
    cudaEventRecord(ev_fork, (cudaStream_t)0);
    cudaStreamWaitEvent(s_side, ev_fork, 0);

    cudaMemsetAsync(hist_ptr, 0, (size_t)(n + 1) * sizeof(int), s_side);
    hist_kernel<<<(ev_threads + 255) / 256, 256, 0, s_side>>>(
        (const int4*)dst, e4, e, dst);
    scan_lookback_kernel<<<nb, SCAN_BLOCK, 0, s_side>>>(n);
    reorder_kernel<<<(ev_threads + 255) / 256, 256, 0, s_side>>>(
        (const int4*)src, (const int4*)dst, e4, e, src, dst);
    cudaEventRecord(ev_join, s_side);

    // ---- main stream: edge-MLP message table (fp16 out) ----
    mlp2_tiled_kernel<__half><<<mlp_blocks, 256, SMEM_BYTES>>>(
        y, W1, b1, W2, b2, mh_ptr, n);

    // ---- join, then aggregate + node MLP ----
    cudaStreamWaitEvent((cudaStream_t)0, ev_join, 0);
    {
        const int blocks = (n * 32 + 255) / 256;
        aggregate_kernel<<<blocks, 256>>>((const __half2*)mh_ptr, (float2*)z_ptr, n);
    }
    mlp2_tiled_kernel<float><<<mlp_blocks, 256, SMEM_BYTES>>>(
        z_ptr, U1, c1, U2, c2, out, n);
}